// round 9
// baseline (speedup 1.0000x reference)
#include <cuda_runtime.h>
#include <cstdint>
#include <math.h>

#define L 256
#define D 128
#define H 4
#define DH 32
#define NROW (L * L)
#define LOG2E 1.4426950408889634f

// ---------------- scratch (device globals; no allocations allowed) ----------
__device__ float g_x[NROW * D];      // LayerNorm output (fp32, row-major)
__device__ float g_xp[NROW * D];     // x in tf32 mma A-fragment order
__device__ float g_qp[NROW * D];     // per-(i,h) A-frag Q (scaled by DH^-0.5*log2e)
__device__ float g_kp[NROW * D];     // per-(i,h) B-frag K^T
__device__ float g_vp[NROW * D];     // per-(i,h) B-frag V
__device__ float g_gate[NROW * D];   // sigmoid(x Wg + bg), row-major
__device__ float g_bias[H * NROW];   // biasT[h][j*L + k] (pre-multiplied by log2e)
__device__ float g_goutp[NROW * D];  // gate*attn_out in A-fragment order
__device__ float g_wp[5 * 16 * 1024];// 5 weights in B-fragment order (tf32)

__device__ __forceinline__ float to_tf32(float x) {
    unsigned int u;
    asm("cvt.rna.tf32.f32 %0, %1;" : "=r"(u) : "f"(x));
    return __uint_as_float(u);
}
__device__ __forceinline__ float fast_ex2(float x) {
    float y;
    asm("ex2.approx.ftz.f32 %0, %1;" : "=f"(y) : "f"(x));
    return y;
}

// ---------------- LayerNorm -------------------------------------------------
__global__ __launch_bounds__(256) void ln_kernel(const float* __restrict__ pair,
                                                 const float* __restrict__ ln_w,
                                                 const float* __restrict__ ln_b) {
    int t = threadIdx.x;
    int lane = t & 31;
    int warp = t >> 5;
    int n = blockIdx.x * 8 + warp;
    const float4 xv = *(const float4*)&pair[(size_t)n * D + lane * 4];
    float s  = xv.x + xv.y + xv.z + xv.w;
    float s2 = xv.x * xv.x + xv.y * xv.y + xv.z * xv.z + xv.w * xv.w;
#pragma unroll
    for (int off = 16; off > 0; off >>= 1) {
        s  += __shfl_xor_sync(0xffffffffu, s,  off);
        s2 += __shfl_xor_sync(0xffffffffu, s2, off);
    }
    float mean = s * (1.0f / 128.0f);
    float var  = s2 * (1.0f / 128.0f) - mean * mean;
    float rstd = rsqrtf(var + 1e-5f);
    float4 w4 = *(const float4*)&ln_w[lane * 4];
    float4 b4 = *(const float4*)&ln_b[lane * 4];
    float4 o;
    o.x = (xv.x - mean) * rstd * w4.x + b4.x;
    o.y = (xv.y - mean) * rstd * w4.y + b4.y;
    o.z = (xv.z - mean) * rstd * w4.z + b4.z;
    o.w = (xv.w - mean) * rstd * w4.w + b4.w;
    *(float4*)&g_x[(size_t)n * D + lane * 4] = o;
}

// ---------------- A-operand permute (16-row tiles, D=128) -------------------
__global__ __launch_bounds__(256) void permute_a_kernel(const float* __restrict__ src,
                                                        float* __restrict__ dst) {
    __shared__ float s[16][132];
    int t = threadIdx.x;
    size_t base = (size_t)blockIdx.x * (16 * 128);
#pragma unroll
    for (int it = 0; it < 2; it++) {
        int f4 = t + it * 256;
        int row = f4 >> 5;
        int c4 = f4 & 31;
        float4 v = *(const float4*)&src[base + row * 128 + c4 * 4];
        s[row][c4 * 4 + 0] = v.x;
        s[row][c4 * 4 + 1] = v.y;
        s[row][c4 * 4 + 2] = v.z;
        s[row][c4 * 4 + 3] = v.w;
    }
    __syncthreads();
    int lane = t & 31;
    int w = t >> 5;
    int g  = lane >> 2;
    int tt = lane & 3;
#pragma unroll
    for (int q = 0; q < 2; q++) {
        int ks = w * 2 + q;
        float4 o;
        o.x = to_tf32(s[g][ks * 8 + tt]);
        o.y = to_tf32(s[g + 8][ks * 8 + tt]);
        o.z = to_tf32(s[g][ks * 8 + tt + 4]);
        o.w = to_tf32(s[g + 8][ks * 8 + tt + 4]);
        *(float4*)&dst[base + ks * 128 + lane * 4] = o;
    }
}

// ---------------- W permute -------------------------------------------------
__global__ __launch_bounds__(256) void permute_w_kernel(const float* __restrict__ Wq,
                                                        const float* __restrict__ Wk,
                                                        const float* __restrict__ Wv,
                                                        const float* __restrict__ Wg,
                                                        const float* __restrict__ Wo) {
    const float* srcs[5] = {Wq, Wk, Wv, Wg, Wo};
    const float* W = srcs[blockIdx.x];
    float* dst = g_wp + blockIdx.x * 16384;
    for (int i = threadIdx.x; i < 16384; i += 256) {
        int kk = i >> 7;
        int n  = i & 127;
        int ks = kk >> 3;
        int nt = n >> 3;
        int lane = (n & 7) * 4 + (kk & 3);
        int reg  = (kk >> 2) & 1;
        dst[ks * 1024 + nt * 64 + lane * 2 + reg] = to_tf32(W[i]);
    }
}

// ---------------- tf32 GEMM with selectable epilogue ------------------------
// mode: 2 = sigmoid(acc+bias[col]) row-major (gate)
//       3 = acc+bias[col] row-major (final out)
//      10 = Q: scale then scatter to per-(i,h) A-frag g_qp
//      11 = K: scatter to per-(i,h) B-frag g_kp
//      12 = V: scatter to per-(i,h) B-frag g_vp
__global__ __launch_bounds__(256) void gemm_tf32_kernel(const float* __restrict__ Xp,
                                                        int wsel,
                                                        float* __restrict__ out,
                                                        int mode,
                                                        const float* __restrict__ bias) {
    __shared__ float As[8][512];
    __shared__ float Bs[4096];

    int t = threadIdx.x;
    int lane = t & 31;
    int warp = t >> 5;
    int warp_m = warp >> 1;
    int warp_n = warp & 1;
    size_t mtb = (size_t)blockIdx.x * 8;
    const float* wp = g_wp + (size_t)wsel * 16384;

    float acc[2][8][4];
#pragma unroll
    for (int wm = 0; wm < 2; wm++)
#pragma unroll
        for (int nt = 0; nt < 8; nt++)
#pragma unroll
            for (int r = 0; r < 4; r++) acc[wm][nt][r] = 0.0f;

    for (int k0s = 0; k0s < 4; k0s++) {
#pragma unroll
        for (int it = 0; it < 4; it++) {
            int f4 = t + it * 256;
            int mt  = f4 >> 7;
            int off = f4 & 127;
            float4 v = *(const float4*)&Xp[((mtb + mt) * 16 + k0s * 4) * 128 + off * 4];
            *(float4*)&As[mt][off * 4] = v;
        }
#pragma unroll
        for (int it = 0; it < 4; it++) {
            int f4 = t + it * 256;
            float4 v = *(const float4*)&wp[k0s * 4096 + f4 * 4];
            *(float4*)&Bs[f4 * 4] = v;
        }
        __syncthreads();

#pragma unroll
        for (int ks = 0; ks < 4; ks++) {
            uint4 afr[2];
            afr[0] = *(const uint4*)&As[warp_m * 2 + 0][ks * 128 + lane * 4];
            afr[1] = *(const uint4*)&As[warp_m * 2 + 1][ks * 128 + lane * 4];
            uint2 bfr[8];
#pragma unroll
            for (int nt = 0; nt < 8; nt++)
                bfr[nt] = *(const uint2*)&Bs[ks * 1024 + (warp_n * 8 + nt) * 64 + lane * 2];
#pragma unroll
            for (int wm = 0; wm < 2; wm++)
#pragma unroll
                for (int nt = 0; nt < 8; nt++) {
                    asm volatile(
                        "mma.sync.aligned.m16n8k8.row.col.f32.tf32.tf32.f32 "
                        "{%0,%1,%2,%3}, {%4,%5,%6,%7}, {%8,%9}, {%0,%1,%2,%3};"
                        : "+f"(acc[wm][nt][0]), "+f"(acc[wm][nt][1]),
                          "+f"(acc[wm][nt][2]), "+f"(acc[wm][nt][3])
                        : "r"(afr[wm].x), "r"(afr[wm].y), "r"(afr[wm].z), "r"(afr[wm].w),
                          "r"(bfr[nt].x), "r"(bfr[nt].y));
                }
        }
        __syncthreads();
    }

    int g   = lane >> 2;
    int tid = lane & 3;
    int m0 = blockIdx.x * 128;

    if (mode >= 10) {
        // direct fragment scatter epilogue (maps validated in R8)
        const float qscale = 0.17677669529663687f * LOG2E;
        float* outbuf = (mode == 10) ? g_qp : (mode == 11) ? g_kp : g_vp;
        int iblk = blockIdx.x >> 1;
        int half = blockIdx.x & 1;
        for (int h = 0; h < 4; h++) {
            if (warp_n == (h >> 1)) {
                int ntbase = (h & 1) * 4;
#pragma unroll
                for (int wm = 0; wm < 2; wm++) {
#pragma unroll
                    for (int ntl = 0; ntl < 4; ntl++) {
                        int nt = ntbase + ntl;
#pragma unroll
                        for (int r = 0; r < 4; r++) {
                            float a = acc[wm][nt][r];
                            int e = (2 * tid + (r & 1)) & 3;
                            int idx;
                            if (mode == 10) {
                                a *= qscale;
                                idx = (warp_m * 2 + wm) * 512 + ntl * 128
                                    + (g * 4 + e) * 4 + (r >> 1) + 2 * (tid >> 1);
                            } else if (mode == 11) {
                                idx = (warp_m * 4 + wm * 2 + (r >> 1)) * 256 + ntl * 64
                                    + (g * 4 + e) * 2 + (tid >> 1);
                            } else {
                                idx = (warp_m * 4 + wm * 2 + (r >> 1)) * 256 + ntl * 64
                                    + ((2 * tid + (r & 1)) * 4 + (g & 3)) * 2 + (g >> 2);
                            }
                            Bs[idx] = to_tf32(a);
                        }
                    }
                }
            }
            __syncthreads();
            float* dst = outbuf + ((size_t)(iblk * 4 + h)) * 8192 + half * 4096;
#pragma unroll
            for (int it = 0; it < 4; it++) {
                int f4 = t + it * 256;
                *(float4*)&dst[f4 * 4] = *(const float4*)&Bs[f4 * 4];
            }
            __syncthreads();
        }
        return;
    }

#pragma unroll
    for (int wm = 0; wm < 2; wm++) {
        int row0 = m0 + warp_m * 32 + wm * 16 + g;
#pragma unroll
        for (int nt = 0; nt < 8; nt++) {
            int col = warp_n * 64 + nt * 8 + tid * 2;
            float b0 = bias[col], b1 = bias[col + 1];
            float v[4];
#pragma unroll
            for (int r = 0; r < 4; r++) {
                float a = acc[wm][nt][r];
                float bb = (r & 1) ? b1 : b0;
                if (mode == 2) a = 1.0f / (1.0f + __expf(-(a + bb)));
                else           a += bb;
                v[r] = a;
            }
            *(float2*)&out[(size_t)row0 * 128 + col]       = make_float2(v[0], v[1]);
            *(float2*)&out[(size_t)(row0 + 8) * 128 + col] = make_float2(v[2], v[3]);
        }
    }
}

// ---------------- bias projection (pre-multiplied by log2e) ----------------
__global__ __launch_bounds__(256) void bias_kernel(const float* __restrict__ Wb) {
    int t = threadIdx.x;
    int lane = t & 31;
    int warp = t >> 5;
    int n = blockIdx.x * 8 + warp;
    float4 xv = *(const float4*)&g_x[(size_t)n * D + lane * 4];
    float xs[4] = {xv.x, xv.y, xv.z, xv.w};
    float p0 = 0.f, p1 = 0.f, p2 = 0.f, p3 = 0.f;
#pragma unroll
    for (int q = 0; q < 4; q++) {
        float4 wb = *(const float4*)&Wb[(lane * 4 + q) * H];
        p0 += xs[q] * wb.x;
        p1 += xs[q] * wb.y;
        p2 += xs[q] * wb.z;
        p3 += xs[q] * wb.w;
    }
#pragma unroll
    for (int off = 16; off > 0; off >>= 1) {
        p0 += __shfl_xor_sync(0xffffffffu, p0, off);
        p1 += __shfl_xor_sync(0xffffffffu, p1, off);
        p2 += __shfl_xor_sync(0xffffffffu, p2, off);
        p3 += __shfl_xor_sync(0xffffffffu, p3, off);
    }
    if (lane == 0) {
        g_bias[0 * NROW + n] = p0 * LOG2E;
        g_bias[1 * NROW + n] = p1 * LOG2E;
        g_bias[2 * NROW + n] = p2 * LOG2E;
        g_bias[3 * NROW + n] = p3 * LOG2E;
    }
}

// ---------------- tensor-core attention -------------------------------------
// grid (i=256, jt=2, h=4); 8 warps; warp handles 16 j-rows. Output written
// directly in A-fragment order (per-warp 512-float contiguous region).
__global__ __launch_bounds__(256) void attn_mma_kernel() {
    __shared__ float Pbuf[8][512];

    int t = threadIdx.x;
    int lane = t & 31;
    int warp = t >> 5;
    int g  = lane >> 2;
    int tq = lane & 3;
    int i  = blockIdx.x;
    int jt = blockIdx.y;
    int h  = blockIdx.z;

    size_t base = ((size_t)(i * 4 + h)) * 8192;
    const float* qp = g_qp + base;
    const float* kp = g_kp + base;
    const float* vp = g_vp + base;

    int mt_global = jt * 8 + warp;
    int j0 = mt_global * 16;

    uint4 qf[4];
#pragma unroll
    for (int ks = 0; ks < 4; ks++)
        qf[ks] = *(const uint4*)&qp[mt_global * 512 + ks * 128 + lane * 4];

    const float* brow0 = g_bias + (size_t)h * NROW + (size_t)(j0 + g) * 256;
    const float* brow1 = brow0 + 8 * 256;

    float lsum0 = 0.f, lsum1 = 0.f;
    float oacc[4][4];
#pragma unroll
    for (int nt = 0; nt < 4; nt++)
#pragma unroll
        for (int r = 0; r < 4; r++) oacc[nt][r] = 0.f;

    float* pb = &Pbuf[warp][0];
    int e0 = (2 * tq) & 3;
    int e1 = (2 * tq + 1) & 3;
    int rb = 2 * (tq >> 1);

    for (int c = 0; c < 8; c++) {
#pragma unroll
        for (int nt = 0; nt < 4; nt++) {
            float sacc[4] = {0.f, 0.f, 0.f, 0.f};
#pragma unroll
            for (int ks = 0; ks < 4; ks++) {
                uint2 bf = *(const uint2*)&kp[(c * 4 + nt) * 256 + ks * 64 + lane * 2];
                asm volatile(
                    "mma.sync.aligned.m16n8k8.row.col.f32.tf32.tf32.f32 "
                    "{%0,%1,%2,%3}, {%4,%5,%6,%7}, {%8,%9}, {%0,%1,%2,%3};"
                    : "+f"(sacc[0]), "+f"(sacc[1]), "+f"(sacc[2]), "+f"(sacc[3])
                    : "r"(qf[ks].x), "r"(qf[ks].y), "r"(qf[ks].z), "r"(qf[ks].w),
                      "r"(bf.x), "r"(bf.y));
            }
            int keyc = c * 32 + nt * 8 + tq * 2;
            float2 b0 = *(const float2*)&brow0[keyc];
            float2 b1 = *(const float2*)&brow1[keyc];
            float p0 = fast_ex2(sacc[0] + b0.x);
            float p1 = fast_ex2(sacc[1] + b0.y);
            float p2 = fast_ex2(sacc[2] + b1.x);
            float p3 = fast_ex2(sacc[3] + b1.y);
            lsum0 += p0 + p1;
            lsum1 += p2 + p3;
            pb[nt * 128 + (g * 4 + e0) * 4 + rb + 0] = p0;
            pb[nt * 128 + (g * 4 + e1) * 4 + rb + 0] = p1;
            pb[nt * 128 + (g * 4 + e0) * 4 + rb + 1] = p2;
            pb[nt * 128 + (g * 4 + e1) * 4 + rb + 1] = p3;
        }
        __syncwarp();
#pragma unroll
        for (int ks = 0; ks < 4; ks++) {
            uint4 pf = *(const uint4*)&pb[ks * 128 + lane * 4];
#pragma unroll
            for (int ntd = 0; ntd < 4; ntd++) {
                uint2 vf = *(const uint2*)&vp[(c * 4 + ks) * 256 + ntd * 64 + lane * 2];
                asm volatile(
                    "mma.sync.aligned.m16n8k8.row.col.f32.tf32.tf32.f32 "
                    "{%0,%1,%2,%3}, {%4,%5,%6,%7}, {%8,%9}, {%0,%1,%2,%3};"
                    : "+f"(oacc[ntd][0]), "+f"(oacc[ntd][1]),
                      "+f"(oacc[ntd][2]), "+f"(oacc[ntd][3])
                    : "r"(pf.x), "r"(pf.y), "r"(pf.z), "r"(pf.w),
                      "r"(vf.x), "r"(vf.y));
            }
        }
        __syncwarp();
    }

    lsum0 += __shfl_xor_sync(0xffffffffu, lsum0, 1);
    lsum0 += __shfl_xor_sync(0xffffffffu, lsum0, 2);
    lsum1 += __shfl_xor_sync(0xffffffffu, lsum1, 1);
    lsum1 += __shfl_xor_sync(0xffffffffu, lsum1, 2);
    float inv0 = 1.0f / lsum0;
    float inv1 = 1.0f / lsum1;

    size_t row0 = (size_t)(i * 256 + j0 + g) * 128 + h * 32;
    size_t row1 = row0 + 8 * 128;
#pragma unroll
    for (int ntd = 0; ntd < 4; ntd++) {
        int col = ntd * 8 + tq * 2;
        float2 g0 = *(const float2*)&g_gate[row0 + col];
        float2 g1 = *(const float2*)&g_gate[row1 + col];
        float v0 = oacc[ntd][0] * inv0 * g0.x;
        float v1 = oacc[ntd][1] * inv0 * g0.y;
        float v2 = oacc[ntd][2] * inv1 * g1.x;
        float v3 = oacc[ntd][3] * inv1 * g1.y;
        pb[ntd * 128 + (g * 4 + e0) * 4 + 0 + 2 * (tq >> 1)] = to_tf32(v0);
        pb[ntd * 128 + (g * 4 + e1) * 4 + 0 + 2 * (tq >> 1)] = to_tf32(v1);
        pb[ntd * 128 + (g * 4 + e0) * 4 + 1 + 2 * (tq >> 1)] = to_tf32(v2);
        pb[ntd * 128 + (g * 4 + e1) * 4 + 1 + 2 * (tq >> 1)] = to_tf32(v3);
    }
    __syncwarp();
    size_t tile = (size_t)(i * 16 + mt_global);
    float* dst = g_goutp + tile * 2048 + h * 512;
#pragma unroll
    for (int q = 0; q < 4; q++) {
        *(float4*)&dst[(q * 32 + lane) * 4] = *(const float4*)&pb[(q * 32 + lane) * 4];
    }
}

// ---------------- launch ----------------------------------------------------
extern "C" void kernel_launch(void* const* d_in, const int* in_sizes, int n_in,
                              void* d_out, int out_size) {
    const float* pair = (const float*)d_in[0];
    const float* ln_w = (const float*)d_in[1];
    const float* ln_b = (const float*)d_in[2];
    const float* Wq   = (const float*)d_in[3];
    const float* Wk   = (const float*)d_in[4];
    const float* Wv   = (const float*)d_in[5];
    const float* Wb   = (const float*)d_in[6];
    const float* Wg   = (const float*)d_in[7];
    const float* bg   = (const float*)d_in[8];
    const float* Wo   = (const float*)d_in[9];
    const float* bo   = (const float*)d_in[10];
    float* out = (float*)d_out;

    float *px, *pxp, *pgate, *pgoutp;
    cudaGetSymbolAddress((void**)&px,     g_x);
    cudaGetSymbolAddress((void**)&pxp,    g_xp);
    cudaGetSymbolAddress((void**)&pgate,  g_gate);
    cudaGetSymbolAddress((void**)&pgoutp, g_goutp);

    ln_kernel<<<NROW / 8, 256>>>(pair, ln_w, ln_b);
    permute_w_kernel<<<5, 256>>>(Wq, Wk, Wv, Wg, Wo);
    permute_a_kernel<<<NROW / 16, 256>>>(px, pxp);

    gemm_tf32_kernel<<<NROW / 128, 256>>>(pxp, 0, nullptr, 10, nullptr);  // Q -> g_qp
    gemm_tf32_kernel<<<NROW / 128, 256>>>(pxp, 1, nullptr, 11, nullptr);  // K -> g_kp
    gemm_tf32_kernel<<<NROW / 128, 256>>>(pxp, 2, nullptr, 12, nullptr);  // V -> g_vp
    gemm_tf32_kernel<<<NROW / 128, 256>>>(pxp, 3, pgate, 2, bg);          // gate
    bias_kernel<<<NROW / 8, 256>>>(Wb);

    attn_mma_kernel<<<dim3(L, 2, H), 256>>>();

    gemm_tf32_kernel<<<NROW / 128, 256>>>(pgoutp, 4, out, 3, bo);
}

// round 10
// speedup vs baseline: 1.2177x; 1.2177x over previous
#include <cuda_runtime.h>
#include <cstdint>
#include <math.h>

#define L 256
#define D 128
#define H 4
#define DH 32
#define NROW (L * L)
#define LOG2E 1.4426950408889634f

// ---------------- scratch (device globals; no allocations allowed) ----------
__device__ float g_xp[NROW * D];     // LN(x) in tf32 mma A-fragment order
__device__ float g_q[NROW * D];      // q row-major (scaled by DH^-0.5*log2e)
__device__ float g_k[NROW * D];
__device__ float g_v[NROW * D];
__device__ float g_qp[NROW * D];     // per-(i,h) A-frag Q
__device__ float g_kp[NROW * D];     // per-(i,h) B-frag K^T
__device__ float g_vp[NROW * D];     // per-(i,h) B-frag V
__device__ float g_gate[NROW * D];   // sigmoid(x Wg + bg), row-major
__device__ float g_bias[H * NROW];   // biasT[h][j*L + k] (pre-multiplied by log2e)
__device__ float g_goutp[NROW * D];  // gate*attn_out in A-fragment order
__device__ float g_wp[5 * 16 * 1024];// 5 weights in B-fragment order (tf32)

__device__ __forceinline__ float to_tf32(float x) {
    unsigned int u;
    asm("cvt.rna.tf32.f32 %0, %1;" : "=r"(u) : "f"(x));
    return __uint_as_float(u);
}
__device__ __forceinline__ float fast_ex2(float x) {
    float y;
    asm("ex2.approx.ftz.f32 %0, %1;" : "=f"(y) : "f"(x));
    return y;
}

// ---------------- fused LN + bias projection + A-fragment write -------------
// Block = 16 rows (one m-tile), 16 warps, warp per row.
__global__ __launch_bounds__(512) void ln_fused_kernel(const float* __restrict__ pair,
                                                       const float* __restrict__ ln_w,
                                                       const float* __restrict__ ln_b,
                                                       const float* __restrict__ Wb) {
    __shared__ float s[16][132];
    int t = threadIdx.x;
    int lane = t & 31;
    int w = t >> 5;                     // 0..15 = row within tile
    int n = blockIdx.x * 16 + w;

    const float4 xv = *(const float4*)&pair[(size_t)n * D + lane * 4];
    float sm  = xv.x + xv.y + xv.z + xv.w;
    float sm2 = xv.x * xv.x + xv.y * xv.y + xv.z * xv.z + xv.w * xv.w;
#pragma unroll
    for (int off = 16; off > 0; off >>= 1) {
        sm  += __shfl_xor_sync(0xffffffffu, sm,  off);
        sm2 += __shfl_xor_sync(0xffffffffu, sm2, off);
    }
    float mean = sm * (1.0f / 128.0f);
    float var  = sm2 * (1.0f / 128.0f) - mean * mean;
    float rstd = rsqrtf(var + 1e-5f);
    float4 w4 = *(const float4*)&ln_w[lane * 4];
    float4 b4 = *(const float4*)&ln_b[lane * 4];
    float o0 = (xv.x - mean) * rstd * w4.x + b4.x;
    float o1 = (xv.y - mean) * rstd * w4.y + b4.y;
    float o2 = (xv.z - mean) * rstd * w4.z + b4.z;
    float o3 = (xv.w - mean) * rstd * w4.w + b4.w;

    // bias projection: dot(x_row, Wb[:,h]) for 4 heads
    {
        float xs[4] = {o0, o1, o2, o3};
        float p0 = 0.f, p1 = 0.f, p2 = 0.f, p3 = 0.f;
#pragma unroll
        for (int q = 0; q < 4; q++) {
            float4 wb = *(const float4*)&Wb[(lane * 4 + q) * H];
            p0 += xs[q] * wb.x;
            p1 += xs[q] * wb.y;
            p2 += xs[q] * wb.z;
            p3 += xs[q] * wb.w;
        }
#pragma unroll
        for (int off = 16; off > 0; off >>= 1) {
            p0 += __shfl_xor_sync(0xffffffffu, p0, off);
            p1 += __shfl_xor_sync(0xffffffffu, p1, off);
            p2 += __shfl_xor_sync(0xffffffffu, p2, off);
            p3 += __shfl_xor_sync(0xffffffffu, p3, off);
        }
        if (lane == 0) {
            g_bias[0 * NROW + n] = p0 * LOG2E;
            g_bias[1 * NROW + n] = p1 * LOG2E;
            g_bias[2 * NROW + n] = p2 * LOG2E;
            g_bias[3 * NROW + n] = p3 * LOG2E;
        }
    }

    s[w][lane * 4 + 0] = o0;
    s[w][lane * 4 + 1] = o1;
    s[w][lane * 4 + 2] = o2;
    s[w][lane * 4 + 3] = o3;
    __syncthreads();

    // A-fragment write (verbatim permute_a map; warp w = ks)
    int g  = lane >> 2;
    int tt = lane & 3;
    int ks = w;
    float4 o;
    o.x = to_tf32(s[g][ks * 8 + tt]);
    o.y = to_tf32(s[g + 8][ks * 8 + tt]);
    o.z = to_tf32(s[g][ks * 8 + tt + 4]);
    o.w = to_tf32(s[g + 8][ks * 8 + tt + 4]);
    *(float4*)&g_xp[(size_t)blockIdx.x * 2048 + ks * 128 + lane * 4] = o;
}

// ---------------- W permute -------------------------------------------------
__global__ __launch_bounds__(256) void permute_w_kernel(const float* __restrict__ Wq,
                                                        const float* __restrict__ Wk,
                                                        const float* __restrict__ Wv,
                                                        const float* __restrict__ Wg,
                                                        const float* __restrict__ Wo) {
    const float* srcs[5] = {Wq, Wk, Wv, Wg, Wo};
    const float* W = srcs[blockIdx.x];
    float* dst = g_wp + blockIdx.x * 16384;
    for (int i = threadIdx.x; i < 16384; i += 256) {
        int kk = i >> 7;
        int n  = i & 127;
        int ks = kk >> 3;
        int nt = n >> 3;
        int lane = (n & 7) * 4 + (kk & 3);
        int reg  = (kk >> 2) & 1;
        dst[ks * 1024 + nt * 64 + lane * 2 + reg] = to_tf32(W[i]);
    }
}

// ---------------- 4 projection GEMMs in one grid-parallel launch ------------
// blockIdx.y selects weight/epilogue: 0=Q(scale), 1=K, 2=V, 3=gate(sigmoid).
__global__ __launch_bounds__(256) void proj_gemm_kernel(const float* __restrict__ Xp,
                                                        const float* __restrict__ bg) {
    __shared__ float As[8][512];
    __shared__ float Bs[4096];

    int t = threadIdx.x;
    int lane = t & 31;
    int warp = t >> 5;
    int warp_m = warp >> 1;
    int warp_n = warp & 1;
    int wsel = blockIdx.y;
    size_t mtb = (size_t)blockIdx.x * 8;
    const float* wp = g_wp + (size_t)wsel * 16384;

    float acc[2][8][4];
#pragma unroll
    for (int wm = 0; wm < 2; wm++)
#pragma unroll
        for (int nt = 0; nt < 8; nt++)
#pragma unroll
            for (int r = 0; r < 4; r++) acc[wm][nt][r] = 0.0f;

    for (int k0s = 0; k0s < 4; k0s++) {
#pragma unroll
        for (int it = 0; it < 4; it++) {
            int f4 = t + it * 256;
            int mt  = f4 >> 7;
            int off = f4 & 127;
            float4 v = *(const float4*)&Xp[((mtb + mt) * 16 + k0s * 4) * 128 + off * 4];
            *(float4*)&As[mt][off * 4] = v;
        }
#pragma unroll
        for (int it = 0; it < 4; it++) {
            int f4 = t + it * 256;
            float4 v = *(const float4*)&wp[k0s * 4096 + f4 * 4];
            *(float4*)&Bs[f4 * 4] = v;
        }
        __syncthreads();

#pragma unroll
        for (int ks = 0; ks < 4; ks++) {
            uint4 afr[2];
            afr[0] = *(const uint4*)&As[warp_m * 2 + 0][ks * 128 + lane * 4];
            afr[1] = *(const uint4*)&As[warp_m * 2 + 1][ks * 128 + lane * 4];
            uint2 bfr[8];
#pragma unroll
            for (int nt = 0; nt < 8; nt++)
                bfr[nt] = *(const uint2*)&Bs[ks * 1024 + (warp_n * 8 + nt) * 64 + lane * 2];
#pragma unroll
            for (int wm = 0; wm < 2; wm++)
#pragma unroll
                for (int nt = 0; nt < 8; nt++) {
                    asm volatile(
                        "mma.sync.aligned.m16n8k8.row.col.f32.tf32.tf32.f32 "
                        "{%0,%1,%2,%3}, {%4,%5,%6,%7}, {%8,%9}, {%0,%1,%2,%3};"
                        : "+f"(acc[wm][nt][0]), "+f"(acc[wm][nt][1]),
                          "+f"(acc[wm][nt][2]), "+f"(acc[wm][nt][3])
                        : "r"(afr[wm].x), "r"(afr[wm].y), "r"(afr[wm].z), "r"(afr[wm].w),
                          "r"(bfr[nt].x), "r"(bfr[nt].y));
                }
        }
        __syncthreads();
    }

    const float qscale = 0.17677669529663687f * LOG2E;
    float* out = (wsel == 0) ? g_q : (wsel == 1) ? g_k : (wsel == 2) ? g_v : g_gate;
    int g   = lane >> 2;
    int tid = lane & 3;
    int m0 = blockIdx.x * 128;
#pragma unroll
    for (int wm = 0; wm < 2; wm++) {
        int row0 = m0 + warp_m * 32 + wm * 16 + g;
#pragma unroll
        for (int nt = 0; nt < 8; nt++) {
            int col = warp_n * 64 + nt * 8 + tid * 2;
            float b0 = 0.f, b1 = 0.f;
            if (wsel == 3) { b0 = bg[col]; b1 = bg[col + 1]; }
            float v[4];
#pragma unroll
            for (int r = 0; r < 4; r++) {
                float a = acc[wm][nt][r];
                if (wsel == 0)      a *= qscale;
                else if (wsel == 3) a = 1.0f / (1.0f + __expf(-(a + ((r & 1) ? b1 : b0))));
                v[r] = a;
            }
            *(float2*)&out[(size_t)row0 * 128 + col]       = make_float2(v[0], v[1]);
            *(float2*)&out[(size_t)(row0 + 8) * 128 + col] = make_float2(v[2], v[3]);
        }
    }
}

// ---------------- attention operand permute: block = (i, h) ----------------
__global__ __launch_bounds__(256) void attn_permute_kernel() {
    __shared__ float s[256][33];
    int t = threadIdx.x;
    int i = blockIdx.x;
    int h = blockIdx.y;
    size_t src_off = ((size_t)i * 256) * 128 + h * 32;
    size_t base = ((size_t)(i * 4 + h)) * 8192;

    const float* sq = g_q + src_off;
    const float* sk = g_k + src_off;
    const float* sv = g_v + src_off;

#pragma unroll 1
    for (int phase = 0; phase < 3; phase++) {
        const float* src = (phase == 0) ? sq : (phase == 1) ? sk : sv;
        float* dst = (phase == 0) ? (g_qp + base) : (phase == 1) ? (g_kp + base) : (g_vp + base);
#pragma unroll
        for (int it = 0; it < 8; it++) {
            int f4 = t + it * 256;
            int r  = f4 >> 3;
            int c4 = f4 & 7;
            float4 v = *(const float4*)&src[(size_t)r * 128 + c4 * 4];
            s[r][c4 * 4 + 0] = v.x;
            s[r][c4 * 4 + 1] = v.y;
            s[r][c4 * 4 + 2] = v.z;
            s[r][c4 * 4 + 3] = v.w;
        }
        __syncthreads();
        if (phase == 0) {
#pragma unroll
            for (int it = 0; it < 32; it++) {
                int idx = it * 256 + t;
                int mt   = idx >> 9;
                int ks   = (idx >> 7) & 3;
                int lane = (idx >> 2) & 31;
                int reg  = idx & 3;
                int j = mt * 16 + (reg & 1) * 8 + (lane >> 2);
                int d = ks * 8 + (reg >> 1) * 4 + (lane & 3);
                dst[idx] = to_tf32(s[j][d]);
            }
        } else if (phase == 1) {
#pragma unroll
            for (int it = 0; it < 32; it++) {
                int idx = it * 256 + t;
                int nt   = idx >> 8;
                int ks   = (idx >> 6) & 3;
                int lane = (idx >> 1) & 31;
                int reg  = idx & 1;
                int key = nt * 8 + (lane >> 2);
                int d   = ks * 8 + reg * 4 + (lane & 3);
                dst[idx] = to_tf32(s[key][d]);
            }
        } else {
#pragma unroll
            for (int it = 0; it < 32; it++) {
                int idx = it * 256 + t;
                int ksk  = idx >> 8;
                int ntd  = (idx >> 6) & 3;
                int lane = (idx >> 1) & 31;
                int reg  = idx & 1;
                int key = ksk * 8 + reg * 4 + (lane & 3);
                int d   = ntd * 8 + (lane >> 2);
                dst[idx] = to_tf32(s[key][d]);
            }
        }
        __syncthreads();
    }
}

// ---------------- tensor-core attention -------------------------------------
__global__ __launch_bounds__(256) void attn_mma_kernel() {
    __shared__ float Pbuf[8][512];

    int t = threadIdx.x;
    int lane = t & 31;
    int warp = t >> 5;
    int g  = lane >> 2;
    int tq = lane & 3;
    int i  = blockIdx.x;
    int jt = blockIdx.y;
    int h  = blockIdx.z;

    size_t base = ((size_t)(i * 4 + h)) * 8192;
    const float* qp = g_qp + base;
    const float* kp = g_kp + base;
    const float* vp = g_vp + base;

    int mt_global = jt * 8 + warp;
    int j0 = mt_global * 16;

    uint4 qf[4];
#pragma unroll
    for (int ks = 0; ks < 4; ks++)
        qf[ks] = *(const uint4*)&qp[mt_global * 512 + ks * 128 + lane * 4];

    const float* brow0 = g_bias + (size_t)h * NROW + (size_t)(j0 + g) * 256;
    const float* brow1 = brow0 + 8 * 256;

    float lsum0 = 0.f, lsum1 = 0.f;
    float oacc[4][4];
#pragma unroll
    for (int nt = 0; nt < 4; nt++)
#pragma unroll
        for (int r = 0; r < 4; r++) oacc[nt][r] = 0.f;

    float* pb = &Pbuf[warp][0];
    int e0 = (2 * tq) & 3;
    int e1 = (2 * tq + 1) & 3;
    int rb = 2 * (tq >> 1);

    for (int c = 0; c < 8; c++) {
#pragma unroll
        for (int nt = 0; nt < 4; nt++) {
            float sacc[4] = {0.f, 0.f, 0.f, 0.f};
#pragma unroll
            for (int ks = 0; ks < 4; ks++) {
                uint2 bf = *(const uint2*)&kp[(c * 4 + nt) * 256 + ks * 64 + lane * 2];
                asm volatile(
                    "mma.sync.aligned.m16n8k8.row.col.f32.tf32.tf32.f32 "
                    "{%0,%1,%2,%3}, {%4,%5,%6,%7}, {%8,%9}, {%0,%1,%2,%3};"
                    : "+f"(sacc[0]), "+f"(sacc[1]), "+f"(sacc[2]), "+f"(sacc[3])
                    : "r"(qf[ks].x), "r"(qf[ks].y), "r"(qf[ks].z), "r"(qf[ks].w),
                      "r"(bf.x), "r"(bf.y));
            }
            int keyc = c * 32 + nt * 8 + tq * 2;
            float2 b0 = *(const float2*)&brow0[keyc];
            float2 b1 = *(const float2*)&brow1[keyc];
            float p0 = fast_ex2(sacc[0] + b0.x);
            float p1 = fast_ex2(sacc[1] + b0.y);
            float p2 = fast_ex2(sacc[2] + b1.x);
            float p3 = fast_ex2(sacc[3] + b1.y);
            lsum0 += p0 + p1;
            lsum1 += p2 + p3;
            pb[nt * 128 + (g * 4 + e0) * 4 + rb + 0] = p0;
            pb[nt * 128 + (g * 4 + e1) * 4 + rb + 0] = p1;
            pb[nt * 128 + (g * 4 + e0) * 4 + rb + 1] = p2;
            pb[nt * 128 + (g * 4 + e1) * 4 + rb + 1] = p3;
        }
        __syncwarp();
#pragma unroll
        for (int ks = 0; ks < 4; ks++) {
            uint4 pf = *(const uint4*)&pb[ks * 128 + lane * 4];
#pragma unroll
            for (int ntd = 0; ntd < 4; ntd++) {
                uint2 vf = *(const uint2*)&vp[(c * 4 + ks) * 256 + ntd * 64 + lane * 2];
                asm volatile(
                    "mma.sync.aligned.m16n8k8.row.col.f32.tf32.tf32.f32 "
                    "{%0,%1,%2,%3}, {%4,%5,%6,%7}, {%8,%9}, {%0,%1,%2,%3};"
                    : "+f"(oacc[ntd][0]), "+f"(oacc[ntd][1]),
                      "+f"(oacc[ntd][2]), "+f"(oacc[ntd][3])
                    : "r"(pf.x), "r"(pf.y), "r"(pf.z), "r"(pf.w),
                      "r"(vf.x), "r"(vf.y));
            }
        }
        __syncwarp();
    }

    lsum0 += __shfl_xor_sync(0xffffffffu, lsum0, 1);
    lsum0 += __shfl_xor_sync(0xffffffffu, lsum0, 2);
    lsum1 += __shfl_xor_sync(0xffffffffu, lsum1, 1);
    lsum1 += __shfl_xor_sync(0xffffffffu, lsum1, 2);
    float inv0 = 1.0f / lsum0;
    float inv1 = 1.0f / lsum1;

    size_t row0 = (size_t)(i * 256 + j0 + g) * 128 + h * 32;
    size_t row1 = row0 + 8 * 128;
#pragma unroll
    for (int ntd = 0; ntd < 4; ntd++) {
        int col = ntd * 8 + tq * 2;
        float2 g0 = *(const float2*)&g_gate[row0 + col];
        float2 g1 = *(const float2*)&g_gate[row1 + col];
        float v0 = oacc[ntd][0] * inv0 * g0.x;
        float v1 = oacc[ntd][1] * inv0 * g0.y;
        float v2 = oacc[ntd][2] * inv1 * g1.x;
        float v3 = oacc[ntd][3] * inv1 * g1.y;
        pb[ntd * 128 + (g * 4 + e0) * 4 + 0 + 2 * (tq >> 1)] = to_tf32(v0);
        pb[ntd * 128 + (g * 4 + e1) * 4 + 0 + 2 * (tq >> 1)] = to_tf32(v1);
        pb[ntd * 128 + (g * 4 + e0) * 4 + 1 + 2 * (tq >> 1)] = to_tf32(v2);
        pb[ntd * 128 + (g * 4 + e1) * 4 + 1 + 2 * (tq >> 1)] = to_tf32(v3);
    }
    __syncwarp();
    size_t tile = (size_t)(i * 16 + mt_global);
    float* dst = g_goutp + tile * 2048 + h * 512;
#pragma unroll
    for (int q = 0; q < 4; q++) {
        *(float4*)&dst[(q * 32 + lane) * 4] = *(const float4*)&pb[(q * 32 + lane) * 4];
    }
}

// ---------------- final output GEMM -----------------------------------------
__global__ __launch_bounds__(256) void gemm_tf32_kernel(const float* __restrict__ Xp,
                                                        int wsel,
                                                        float* __restrict__ out,
                                                        const float* __restrict__ bias) {
    __shared__ float As[8][512];
    __shared__ float Bs[4096];

    int t = threadIdx.x;
    int lane = t & 31;
    int warp = t >> 5;
    int warp_m = warp >> 1;
    int warp_n = warp & 1;
    size_t mtb = (size_t)blockIdx.x * 8;
    const float* wp = g_wp + (size_t)wsel * 16384;

    float acc[2][8][4];
#pragma unroll
    for (int wm = 0; wm < 2; wm++)
#pragma unroll
        for (int nt = 0; nt < 8; nt++)
#pragma unroll
            for (int r = 0; r < 4; r++) acc[wm][nt][r] = 0.0f;

    for (int k0s = 0; k0s < 4; k0s++) {
#pragma unroll
        for (int it = 0; it < 4; it++) {
            int f4 = t + it * 256;
            int mt  = f4 >> 7;
            int off = f4 & 127;
            float4 v = *(const float4*)&Xp[((mtb + mt) * 16 + k0s * 4) * 128 + off * 4];
            *(float4*)&As[mt][off * 4] = v;
        }
#pragma unroll
        for (int it = 0; it < 4; it++) {
            int f4 = t + it * 256;
            float4 v = *(const float4*)&wp[k0s * 4096 + f4 * 4];
            *(float4*)&Bs[f4 * 4] = v;
        }
        __syncthreads();

#pragma unroll
        for (int ks = 0; ks < 4; ks++) {
            uint4 afr[2];
            afr[0] = *(const uint4*)&As[warp_m * 2 + 0][ks * 128 + lane * 4];
            afr[1] = *(const uint4*)&As[warp_m * 2 + 1][ks * 128 + lane * 4];
            uint2 bfr[8];
#pragma unroll
            for (int nt = 0; nt < 8; nt++)
                bfr[nt] = *(const uint2*)&Bs[ks * 1024 + (warp_n * 8 + nt) * 64 + lane * 2];
#pragma unroll
            for (int wm = 0; wm < 2; wm++)
#pragma unroll
                for (int nt = 0; nt < 8; nt++) {
                    asm volatile(
                        "mma.sync.aligned.m16n8k8.row.col.f32.tf32.tf32.f32 "
                        "{%0,%1,%2,%3}, {%4,%5,%6,%7}, {%8,%9}, {%0,%1,%2,%3};"
                        : "+f"(acc[wm][nt][0]), "+f"(acc[wm][nt][1]),
                          "+f"(acc[wm][nt][2]), "+f"(acc[wm][nt][3])
                        : "r"(afr[wm].x), "r"(afr[wm].y), "r"(afr[wm].z), "r"(afr[wm].w),
                          "r"(bfr[nt].x), "r"(bfr[nt].y));
                }
        }
        __syncthreads();
    }

    int g   = lane >> 2;
    int tid = lane & 3;
    int m0 = blockIdx.x * 128;
#pragma unroll
    for (int wm = 0; wm < 2; wm++) {
        int row0 = m0 + warp_m * 32 + wm * 16 + g;
#pragma unroll
        for (int nt = 0; nt < 8; nt++) {
            int col = warp_n * 64 + nt * 8 + tid * 2;
            float b0 = bias[col], b1 = bias[col + 1];
            *(float2*)&out[(size_t)row0 * 128 + col] =
                make_float2(acc[wm][nt][0] + b0, acc[wm][nt][1] + b1);
            *(float2*)&out[(size_t)(row0 + 8) * 128 + col] =
                make_float2(acc[wm][nt][2] + b0, acc[wm][nt][3] + b1);
        }
    }
}

// ---------------- launch ----------------------------------------------------
extern "C" void kernel_launch(void* const* d_in, const int* in_sizes, int n_in,
                              void* d_out, int out_size) {
    const float* pair = (const float*)d_in[0];
    const float* ln_w = (const float*)d_in[1];
    const float* ln_b = (const float*)d_in[2];
    const float* Wq   = (const float*)d_in[3];
    const float* Wk   = (const float*)d_in[4];
    const float* Wv   = (const float*)d_in[5];
    const float* Wb   = (const float*)d_in[6];
    const float* Wg   = (const float*)d_in[7];
    const float* bg   = (const float*)d_in[8];
    const float* Wo   = (const float*)d_in[9];
    const float* bo   = (const float*)d_in[10];
    float* out = (float*)d_out;

    float *pxp, *pgoutp;
    cudaGetSymbolAddress((void**)&pxp,    g_xp);
    cudaGetSymbolAddress((void**)&pgoutp, g_goutp);

    ln_fused_kernel<<<NROW / 16, 512>>>(pair, ln_w, ln_b, Wb);
    permute_w_kernel<<<5, 256>>>(Wq, Wk, Wv, Wg, Wo);

    proj_gemm_kernel<<<dim3(NROW / 128, 4), 256>>>(pxp, bg);

    attn_permute_kernel<<<dim3(L, H), 256>>>();
    attn_mma_kernel<<<dim3(L, 2, H), 256>>>();

    gemm_tf32_kernel<<<NROW / 128, 256>>>(pgoutp, 4, out, bo);
}

// round 12
// speedup vs baseline: 1.4192x; 1.1655x over previous
#include <cuda_runtime.h>
#include <cstdint>
#include <math.h>

#define L 256
#define D 128
#define H 4
#define DH 32
#define NROW (L * L)
#define LOG2E 1.4426950408889634f

// ---------------- scratch (device globals; no allocations allowed) ----------
__device__ float g_xp[NROW * D];     // LN(x) in tf32 mma A-fragment order
__device__ float g_q[NROW * D];      // q row-major (scaled by DH^-0.5*log2e)
__device__ float g_k[NROW * D];
__device__ float g_v[NROW * D];
__device__ float g_qp[NROW * D];     // per-(i,h) A-frag Q
__device__ float g_kp[NROW * D];     // per-(i,h) B-frag K^T
__device__ float g_vp[NROW * D];     // per-(i,h) B-frag V
__device__ float g_gate[NROW * D];   // sigmoid(x Wg + bg), row-major
__device__ float g_bias[H * NROW];   // biasT[h][j*L + k] (pre-multiplied by log2e)
__device__ float g_goutp[NROW * D];  // gate*attn_out in A-fragment order
__device__ float g_wp[5 * 16 * 1024];// 5 weights in B-fragment order (tf32)

__device__ __forceinline__ float to_tf32(float x) {
    unsigned int u;
    asm("cvt.rna.tf32.f32 %0, %1;" : "=r"(u) : "f"(x));
    return __uint_as_float(u);
}
__device__ __forceinline__ float fast_ex2(float x) {
    float y;
    asm("ex2.approx.ftz.f32 %0, %1;" : "=f"(y) : "f"(x));
    return y;
}

// ---------------- fused LN + bias projection + A-fragment write -------------
__global__ __launch_bounds__(512) void ln_fused_kernel(const float* __restrict__ pair,
                                                       const float* __restrict__ ln_w,
                                                       const float* __restrict__ ln_b,
                                                       const float* __restrict__ Wb) {
    __shared__ float s[16][132];
    int t = threadIdx.x;
    int lane = t & 31;
    int w = t >> 5;
    int n = blockIdx.x * 16 + w;

    const float4 xv = *(const float4*)&pair[(size_t)n * D + lane * 4];
    float sm  = xv.x + xv.y + xv.z + xv.w;
    float sm2 = xv.x * xv.x + xv.y * xv.y + xv.z * xv.z + xv.w * xv.w;
#pragma unroll
    for (int off = 16; off > 0; off >>= 1) {
        sm  += __shfl_xor_sync(0xffffffffu, sm,  off);
        sm2 += __shfl_xor_sync(0xffffffffu, sm2, off);
    }
    float mean = sm * (1.0f / 128.0f);
    float var  = sm2 * (1.0f / 128.0f) - mean * mean;
    float rstd = rsqrtf(var + 1e-5f);
    float4 w4 = *(const float4*)&ln_w[lane * 4];
    float4 b4 = *(const float4*)&ln_b[lane * 4];
    float o0 = (xv.x - mean) * rstd * w4.x + b4.x;
    float o1 = (xv.y - mean) * rstd * w4.y + b4.y;
    float o2 = (xv.z - mean) * rstd * w4.z + b4.z;
    float o3 = (xv.w - mean) * rstd * w4.w + b4.w;

    {
        float xs[4] = {o0, o1, o2, o3};
        float p0 = 0.f, p1 = 0.f, p2 = 0.f, p3 = 0.f;
#pragma unroll
        for (int q = 0; q < 4; q++) {
            float4 wb = *(const float4*)&Wb[(lane * 4 + q) * H];
            p0 += xs[q] * wb.x;
            p1 += xs[q] * wb.y;
            p2 += xs[q] * wb.z;
            p3 += xs[q] * wb.w;
        }
#pragma unroll
        for (int off = 16; off > 0; off >>= 1) {
            p0 += __shfl_xor_sync(0xffffffffu, p0, off);
            p1 += __shfl_xor_sync(0xffffffffu, p1, off);
            p2 += __shfl_xor_sync(0xffffffffu, p2, off);
            p3 += __shfl_xor_sync(0xffffffffu, p3, off);
        }
        if (lane == 0) {
            g_bias[0 * NROW + n] = p0 * LOG2E;
            g_bias[1 * NROW + n] = p1 * LOG2E;
            g_bias[2 * NROW + n] = p2 * LOG2E;
            g_bias[3 * NROW + n] = p3 * LOG2E;
        }
    }

    s[w][lane * 4 + 0] = o0;
    s[w][lane * 4 + 1] = o1;
    s[w][lane * 4 + 2] = o2;
    s[w][lane * 4 + 3] = o3;
    __syncthreads();

    int g  = lane >> 2;
    int tt = lane & 3;
    int ks = w;
    float4 o;
    o.x = to_tf32(s[g][ks * 8 + tt]);
    o.y = to_tf32(s[g + 8][ks * 8 + tt]);
    o.z = to_tf32(s[g][ks * 8 + tt + 4]);
    o.w = to_tf32(s[g + 8][ks * 8 + tt + 4]);
    *(float4*)&g_xp[(size_t)blockIdx.x * 2048 + ks * 128 + lane * 4] = o;
}

// ---------------- W permute -------------------------------------------------
__global__ __launch_bounds__(256) void permute_w_kernel(const float* __restrict__ Wq,
                                                        const float* __restrict__ Wk,
                                                        const float* __restrict__ Wv,
                                                        const float* __restrict__ Wg,
                                                        const float* __restrict__ Wo) {
    const float* srcs[5] = {Wq, Wk, Wv, Wg, Wo};
    const float* W = srcs[blockIdx.x];
    float* dst = g_wp + blockIdx.x * 16384;
    for (int i = threadIdx.x; i < 16384; i += 256) {
        int kk = i >> 7;
        int n  = i & 127;
        int ks = kk >> 3;
        int nt = n >> 3;
        int lane = (n & 7) * 4 + (kk & 3);
        int reg  = (kk >> 2) & 1;
        dst[ks * 1024 + nt * 64 + lane * 2 + reg] = to_tf32(W[i]);
    }
}

// ---------------- 4 projection GEMMs in one grid-parallel launch ------------
__global__ __launch_bounds__(256) void proj_gemm_kernel(const float* __restrict__ Xp,
                                                        const float* __restrict__ bg) {
    __shared__ float As[8][512];
    __shared__ float Bs[4096];

    int t = threadIdx.x;
    int lane = t & 31;
    int warp = t >> 5;
    int warp_m = warp >> 1;
    int warp_n = warp & 1;
    int wsel = blockIdx.y;
    size_t mtb = (size_t)blockIdx.x * 8;
    const float* wp = g_wp + (size_t)wsel * 16384;

    float acc[2][8][4];
#pragma unroll
    for (int wm = 0; wm < 2; wm++)
#pragma unroll
        for (int nt = 0; nt < 8; nt++)
#pragma unroll
            for (int r = 0; r < 4; r++) acc[wm][nt][r] = 0.0f;

    for (int k0s = 0; k0s < 4; k0s++) {
#pragma unroll
        for (int it = 0; it < 4; it++) {
            int f4 = t + it * 256;
            int mt  = f4 >> 7;
            int off = f4 & 127;
            float4 v = *(const float4*)&Xp[((mtb + mt) * 16 + k0s * 4) * 128 + off * 4];
            *(float4*)&As[mt][off * 4] = v;
        }
#pragma unroll
        for (int it = 0; it < 4; it++) {
            int f4 = t + it * 256;
            float4 v = *(const float4*)&wp[k0s * 4096 + f4 * 4];
            *(float4*)&Bs[f4 * 4] = v;
        }
        __syncthreads();

#pragma unroll
        for (int ks = 0; ks < 4; ks++) {
            uint4 afr[2];
            afr[0] = *(const uint4*)&As[warp_m * 2 + 0][ks * 128 + lane * 4];
            afr[1] = *(const uint4*)&As[warp_m * 2 + 1][ks * 128 + lane * 4];
            uint2 bfr[8];
#pragma unroll
            for (int nt = 0; nt < 8; nt++)
                bfr[nt] = *(const uint2*)&Bs[ks * 1024 + (warp_n * 8 + nt) * 64 + lane * 2];
#pragma unroll
            for (int wm = 0; wm < 2; wm++)
#pragma unroll
                for (int nt = 0; nt < 8; nt++) {
                    asm volatile(
                        "mma.sync.aligned.m16n8k8.row.col.f32.tf32.tf32.f32 "
                        "{%0,%1,%2,%3}, {%4,%5,%6,%7}, {%8,%9}, {%0,%1,%2,%3};"
                        : "+f"(acc[wm][nt][0]), "+f"(acc[wm][nt][1]),
                          "+f"(acc[wm][nt][2]), "+f"(acc[wm][nt][3])
                        : "r"(afr[wm].x), "r"(afr[wm].y), "r"(afr[wm].z), "r"(afr[wm].w),
                          "r"(bfr[nt].x), "r"(bfr[nt].y));
                }
        }
        __syncthreads();
    }

    const float qscale = 0.17677669529663687f * LOG2E;
    float* out = (wsel == 0) ? g_q : (wsel == 1) ? g_k : (wsel == 2) ? g_v : g_gate;
    int g   = lane >> 2;
    int tid = lane & 3;
    int m0 = blockIdx.x * 128;
#pragma unroll
    for (int wm = 0; wm < 2; wm++) {
        int row0 = m0 + warp_m * 32 + wm * 16 + g;
#pragma unroll
        for (int nt = 0; nt < 8; nt++) {
            int col = warp_n * 64 + nt * 8 + tid * 2;
            float b0 = 0.f, b1 = 0.f;
            if (wsel == 3) { b0 = bg[col]; b1 = bg[col + 1]; }
            float v[4];
#pragma unroll
            for (int r = 0; r < 4; r++) {
                float a = acc[wm][nt][r];
                if (wsel == 0)      a *= qscale;
                else if (wsel == 3) a = 1.0f / (1.0f + __expf(-(a + ((r & 1) ? b1 : b0))));
                v[r] = a;
            }
            *(float2*)&out[(size_t)row0 * 128 + col]       = make_float2(v[0], v[1]);
            *(float2*)&out[(size_t)(row0 + 8) * 128 + col] = make_float2(v[2], v[3]);
        }
    }
}

// ---------------- attention operand permute: block = (i, h) ----------------
__global__ __launch_bounds__(256) void attn_permute_kernel() {
    __shared__ float s[256][33];
    int t = threadIdx.x;
    int i = blockIdx.x;
    int h = blockIdx.y;
    size_t src_off = ((size_t)i * 256) * 128 + h * 32;
    size_t base = ((size_t)(i * 4 + h)) * 8192;

    const float* sq = g_q + src_off;
    const float* sk = g_k + src_off;
    const float* sv = g_v + src_off;

#pragma unroll 1
    for (int phase = 0; phase < 3; phase++) {
        const float* src = (phase == 0) ? sq : (phase == 1) ? sk : sv;
        float* dst = (phase == 0) ? (g_qp + base) : (phase == 1) ? (g_kp + base) : (g_vp + base);
#pragma unroll
        for (int it = 0; it < 8; it++) {
            int f4 = t + it * 256;
            int r  = f4 >> 3;
            int c4 = f4 & 7;
            float4 v = *(const float4*)&src[(size_t)r * 128 + c4 * 4];
            s[r][c4 * 4 + 0] = v.x;
            s[r][c4 * 4 + 1] = v.y;
            s[r][c4 * 4 + 2] = v.z;
            s[r][c4 * 4 + 3] = v.w;
        }
        __syncthreads();
        if (phase == 0) {
#pragma unroll
            for (int it = 0; it < 32; it++) {
                int idx = it * 256 + t;
                int mt   = idx >> 9;
                int ks   = (idx >> 7) & 3;
                int lane = (idx >> 2) & 31;
                int reg  = idx & 3;
                int j = mt * 16 + (reg & 1) * 8 + (lane >> 2);
                int d = ks * 8 + (reg >> 1) * 4 + (lane & 3);
                dst[idx] = to_tf32(s[j][d]);
            }
        } else if (phase == 1) {
#pragma unroll
            for (int it = 0; it < 32; it++) {
                int idx = it * 256 + t;
                int nt   = idx >> 8;
                int ks   = (idx >> 6) & 3;
                int lane = (idx >> 1) & 31;
                int reg  = idx & 1;
                int key = nt * 8 + (lane >> 2);
                int d   = ks * 8 + reg * 4 + (lane & 3);
                dst[idx] = to_tf32(s[key][d]);
            }
        } else {
#pragma unroll
            for (int it = 0; it < 32; it++) {
                int idx = it * 256 + t;
                int ksk  = idx >> 8;
                int ntd  = (idx >> 6) & 3;
                int lane = (idx >> 1) & 31;
                int reg  = idx & 1;
                int key = ksk * 8 + reg * 4 + (lane & 3);
                int d   = ntd * 8 + (lane >> 2);
                dst[idx] = to_tf32(s[key][d]);
            }
        }
        __syncthreads();
    }
}

// ---------------- tensor-core attention (K/V staged in shared) --------------
// grid (i=256, jt=2, h=4); 8 warps; warp handles 16 j-rows.
// smem: Ks[8192] + Vs[8192] + Pbuf[8*512] = 80 KB dynamic.
__global__ __launch_bounds__(256) void attn_mma_kernel() {
    extern __shared__ float sh[];
    float* Ks   = sh;              // 8192: B-frag K^T
    float* Vs   = sh + 8192;       // 8192: B-frag V
    float* Pall = sh + 16384;      // 8*512 per-warp P staging

    int t = threadIdx.x;
    int lane = t & 31;
    int warp = t >> 5;
    int g  = lane >> 2;
    int tq = lane & 3;
    int i  = blockIdx.x;
    int jt = blockIdx.y;
    int h  = blockIdx.z;

    size_t base = ((size_t)(i * 4 + h)) * 8192;
    const float* qp = g_qp + base;
    const float* kp = g_kp + base;
    const float* vp = g_vp + base;

    // stage K and V fragment buffers (coalesced; 2048 float4 each)
#pragma unroll
    for (int it = 0; it < 8; it++) {
        int f4 = t + it * 256;
        *(float4*)&Ks[f4 * 4] = *(const float4*)&kp[f4 * 4];
    }
#pragma unroll
    for (int it = 0; it < 8; it++) {
        int f4 = t + it * 256;
        *(float4*)&Vs[f4 * 4] = *(const float4*)&vp[f4 * 4];
    }

    int mt_global = jt * 8 + warp;
    int j0 = mt_global * 16;

    uint4 qf[4];
#pragma unroll
    for (int ks = 0; ks < 4; ks++)
        qf[ks] = *(const uint4*)&qp[mt_global * 512 + ks * 128 + lane * 4];

    const float* brow0 = g_bias + (size_t)h * NROW + (size_t)(j0 + g) * 256;
    const float* brow1 = brow0 + 8 * 256;

    float lsum0 = 0.f, lsum1 = 0.f;
    float oacc[4][4];
#pragma unroll
    for (int nt = 0; nt < 4; nt++)
#pragma unroll
        for (int r = 0; r < 4; r++) oacc[nt][r] = 0.f;

    float* pb = &Pall[warp * 512];
    int e0 = (2 * tq) & 3;
    int e1 = (2 * tq + 1) & 3;
    int rb = 2 * (tq >> 1);

    __syncthreads();

    for (int c = 0; c < 8; c++) {
#pragma unroll
        for (int nt = 0; nt < 4; nt++) {
            float sacc[4] = {0.f, 0.f, 0.f, 0.f};
#pragma unroll
            for (int ks = 0; ks < 4; ks++) {
                uint2 bf = *(const uint2*)&Ks[(c * 4 + nt) * 256 + ks * 64 + lane * 2];
                asm volatile(
                    "mma.sync.aligned.m16n8k8.row.col.f32.tf32.tf32.f32 "
                    "{%0,%1,%2,%3}, {%4,%5,%6,%7}, {%8,%9}, {%0,%1,%2,%3};"
                    : "+f"(sacc[0]), "+f"(sacc[1]), "+f"(sacc[2]), "+f"(sacc[3])
                    : "r"(qf[ks].x), "r"(qf[ks].y), "r"(qf[ks].z), "r"(qf[ks].w),
                      "r"(bf.x), "r"(bf.y));
            }
            int keyc = c * 32 + nt * 8 + tq * 2;
            float2 b0 = *(const float2*)&brow0[keyc];
            float2 b1 = *(const float2*)&brow1[keyc];
            float p0 = fast_ex2(sacc[0] + b0.x);
            float p1 = fast_ex2(sacc[1] + b0.y);
            float p2 = fast_ex2(sacc[2] + b1.x);
            float p3 = fast_ex2(sacc[3] + b1.y);
            lsum0 += p0 + p1;
            lsum1 += p2 + p3;
            pb[nt * 128 + (g * 4 + e0) * 4 + rb + 0] = p0;
            pb[nt * 128 + (g * 4 + e1) * 4 + rb + 0] = p1;
            pb[nt * 128 + (g * 4 + e0) * 4 + rb + 1] = p2;
            pb[nt * 128 + (g * 4 + e1) * 4 + rb + 1] = p3;
        }
        __syncwarp();
#pragma unroll
        for (int ks = 0; ks < 4; ks++) {
            uint4 pf = *(const uint4*)&pb[ks * 128 + lane * 4];
#pragma unroll
            for (int ntd = 0; ntd < 4; ntd++) {
                uint2 vf = *(const uint2*)&Vs[(c * 4 + ks) * 256 + ntd * 64 + lane * 2];
                asm volatile(
                    "mma.sync.aligned.m16n8k8.row.col.f32.tf32.tf32.f32 "
                    "{%0,%1,%2,%3}, {%4,%5,%6,%7}, {%8,%9}, {%0,%1,%2,%3};"
                    : "+f"(oacc[ntd][0]), "+f"(oacc[ntd][1]),
                      "+f"(oacc[ntd][2]), "+f"(oacc[ntd][3])
                    : "r"(pf.x), "r"(pf.y), "r"(pf.z), "r"(pf.w),
                      "r"(vf.x), "r"(vf.y));
            }
        }
        __syncwarp();
    }

    lsum0 += __shfl_xor_sync(0xffffffffu, lsum0, 1);
    lsum0 += __shfl_xor_sync(0xffffffffu, lsum0, 2);
    lsum1 += __shfl_xor_sync(0xffffffffu, lsum1, 1);
    lsum1 += __shfl_xor_sync(0xffffffffu, lsum1, 2);
    float inv0 = 1.0f / lsum0;
    float inv1 = 1.0f / lsum1;

    size_t row0 = (size_t)(i * 256 + j0 + g) * 128 + h * 32;
    size_t row1 = row0 + 8 * 128;
#pragma unroll
    for (int ntd = 0; ntd < 4; ntd++) {
        int col = ntd * 8 + tq * 2;
        float2 g0 = *(const float2*)&g_gate[row0 + col];
        float2 g1 = *(const float2*)&g_gate[row1 + col];
        float v0 = oacc[ntd][0] * inv0 * g0.x;
        float v1 = oacc[ntd][1] * inv0 * g0.y;
        float v2 = oacc[ntd][2] * inv1 * g1.x;
        float v3 = oacc[ntd][3] * inv1 * g1.y;
        pb[ntd * 128 + (g * 4 + e0) * 4 + 0 + 2 * (tq >> 1)] = to_tf32(v0);
        pb[ntd * 128 + (g * 4 + e1) * 4 + 0 + 2 * (tq >> 1)] = to_tf32(v1);
        pb[ntd * 128 + (g * 4 + e0) * 4 + 1 + 2 * (tq >> 1)] = to_tf32(v2);
        pb[ntd * 128 + (g * 4 + e1) * 4 + 1 + 2 * (tq >> 1)] = to_tf32(v3);
    }
    __syncwarp();
    size_t tile = (size_t)(i * 16 + mt_global);
    float* dst = g_goutp + tile * 2048 + h * 512;
#pragma unroll
    for (int q = 0; q < 4; q++) {
        *(float4*)&dst[(q * 32 + lane) * 4] = *(const float4*)&pb[(q * 32 + lane) * 4];
    }
}

// ---------------- final output GEMM -----------------------------------------
__global__ __launch_bounds__(256) void gemm_tf32_kernel(const float* __restrict__ Xp,
                                                        int wsel,
                                                        float* __restrict__ out,
                                                        const float* __restrict__ bias) {
    __shared__ float As[8][512];
    __shared__ float Bs[4096];

    int t = threadIdx.x;
    int lane = t & 31;
    int warp = t >> 5;
    int warp_m = warp >> 1;
    int warp_n = warp & 1;
    size_t mtb = (size_t)blockIdx.x * 8;
    const float* wp = g_wp + (size_t)wsel * 16384;

    float acc[2][8][4];
#pragma unroll
    for (int wm = 0; wm < 2; wm++)
#pragma unroll
        for (int nt = 0; nt < 8; nt++)
#pragma unroll
            for (int r = 0; r < 4; r++) acc[wm][nt][r] = 0.0f;

    for (int k0s = 0; k0s < 4; k0s++) {
#pragma unroll
        for (int it = 0; it < 4; it++) {
            int f4 = t + it * 256;
            int mt  = f4 >> 7;
            int off = f4 & 127;
            float4 v = *(const float4*)&Xp[((mtb + mt) * 16 + k0s * 4) * 128 + off * 4];
            *(float4*)&As[mt][off * 4] = v;
        }
#pragma unroll
        for (int it = 0; it < 4; it++) {
            int f4 = t + it * 256;
            float4 v = *(const float4*)&wp[k0s * 4096 + f4 * 4];
            *(float4*)&Bs[f4 * 4] = v;
        }
        __syncthreads();

#pragma unroll
        for (int ks = 0; ks < 4; ks++) {
            uint4 afr[2];
            afr[0] = *(const uint4*)&As[warp_m * 2 + 0][ks * 128 + lane * 4];
            afr[1] = *(const uint4*)&As[warp_m * 2 + 1][ks * 128 + lane * 4];
            uint2 bfr[8];
#pragma unroll
            for (int nt = 0; nt < 8; nt++)
                bfr[nt] = *(const uint2*)&Bs[ks * 1024 + (warp_n * 8 + nt) * 64 + lane * 2];
#pragma unroll
            for (int wm = 0; wm < 2; wm++)
#pragma unroll
                for (int nt = 0; nt < 8; nt++) {
                    asm volatile(
                        "mma.sync.aligned.m16n8k8.row.col.f32.tf32.tf32.f32 "
                        "{%0,%1,%2,%3}, {%4,%5,%6,%7}, {%8,%9}, {%0,%1,%2,%3};"
                        : "+f"(acc[wm][nt][0]), "+f"(acc[wm][nt][1]),
                          "+f"(acc[wm][nt][2]), "+f"(acc[wm][nt][3])
                        : "r"(afr[wm].x), "r"(afr[wm].y), "r"(afr[wm].z), "r"(afr[wm].w),
                          "r"(bfr[nt].x), "r"(bfr[nt].y));
                }
        }
        __syncthreads();
    }

    int g   = lane >> 2;
    int tid = lane & 3;
    int m0 = blockIdx.x * 128;
#pragma unroll
    for (int wm = 0; wm < 2; wm++) {
        int row0 = m0 + warp_m * 32 + wm * 16 + g;
#pragma unroll
        for (int nt = 0; nt < 8; nt++) {
            int col = warp_n * 64 + nt * 8 + tid * 2;
            float b0 = bias[col], b1 = bias[col + 1];
            *(float2*)&out[(size_t)row0 * 128 + col] =
                make_float2(acc[wm][nt][0] + b0, acc[wm][nt][1] + b1);
            *(float2*)&out[(size_t)(row0 + 8) * 128 + col] =
                make_float2(acc[wm][nt][2] + b0, acc[wm][nt][3] + b1);
        }
    }
}

// ---------------- launch ----------------------------------------------------
extern "C" void kernel_launch(void* const* d_in, const int* in_sizes, int n_in,
                              void* d_out, int out_size) {
    const float* pair = (const float*)d_in[0];
    const float* ln_w = (const float*)d_in[1];
    const float* ln_b = (const float*)d_in[2];
    const float* Wq   = (const float*)d_in[3];
    const float* Wk   = (const float*)d_in[4];
    const float* Wv   = (const float*)d_in[5];
    const float* Wb   = (const float*)d_in[6];
    const float* Wg   = (const float*)d_in[7];
    const float* bg   = (const float*)d_in[8];
    const float* Wo   = (const float*)d_in[9];
    const float* bo   = (const float*)d_in[10];
    float* out = (float*)d_out;

    float *pxp, *pgoutp;
    cudaGetSymbolAddress((void**)&pxp,    g_xp);
    cudaGetSymbolAddress((void**)&pgoutp, g_goutp);

    cudaFuncSetAttribute(attn_mma_kernel, cudaFuncAttributeMaxDynamicSharedMemorySize,
                         (8192 + 8192 + 8 * 512) * (int)sizeof(float));

    ln_fused_kernel<<<NROW / 16, 512>>>(pair, ln_w, ln_b, Wb);
    permute_w_kernel<<<5, 256>>>(Wq, Wk, Wv, Wg, Wo);

    proj_gemm_kernel<<<dim3(NROW / 128, 4), 256>>>(pxp, bg);

    attn_permute_kernel<<<dim3(L, H), 256>>>();
    attn_mma_kernel<<<dim3(L, 2, H), 256,
                      (8192 + 8192 + 8 * 512) * sizeof(float)>>>();

    gemm_tf32_kernel<<<NROW / 128, 256>>>(pgoutp, 4, out, bo);
}

// round 15
// speedup vs baseline: 1.7346x; 1.2222x over previous
#include <cuda_runtime.h>
#include <cuda_fp16.h>
#include <cstdint>
#include <math.h>

#define L 256
#define D 128
#define H 4
#define DH 32
#define NROW (L * L)
#define LOG2E 1.4426950408889634f

// ---------------- scratch (device globals; no allocations allowed) ----------
__device__ float g_xp[NROW * D];      // LN(x) in tf32 mma A-fragment order
__device__ float g_q[NROW * D];       // q row-major (scaled by DH^-0.5*log2e)
__device__ float g_k[NROW * D];
__device__ float g_v[NROW * D];
__device__ unsigned int g_qp16[NROW * D / 2]; // per-(i,h) fp16 A-frag Q (packed half2)
__device__ unsigned int g_kp16[NROW * D / 2]; // per-(i,h) fp16 B-frag K^T
__device__ unsigned int g_vp16[NROW * D / 2]; // per-(i,h) fp16 B-frag V
__device__ float g_gate[NROW * D];    // sigmoid(x Wg + bg), row-major
__device__ float g_bias[H * NROW];    // biasT[h][j*L + k] (pre-multiplied by log2e)
__device__ float g_goutp[NROW * D];   // gate*attn_out in tf32 A-fragment order
__device__ float g_wp[5 * 16 * 1024]; // 5 weights in tf32 B-fragment order

__device__ __forceinline__ float to_tf32(float x) {
    unsigned int u;
    asm("cvt.rna.tf32.f32 %0, %1;" : "=r"(u) : "f"(x));
    return __uint_as_float(u);
}
__device__ __forceinline__ float fast_ex2(float x) {
    float y;
    asm("ex2.approx.ftz.f32 %0, %1;" : "=f"(y) : "f"(x));
    return y;
}
__device__ __forceinline__ unsigned int pack_h2(float lo, float hi) {
    __half2 h = __floats2half2_rn(lo, hi);
    return *reinterpret_cast<unsigned int*>(&h);
}

// ---------------- fused LN + bias projection + A-fragment write -------------
__global__ __launch_bounds__(512) void ln_fused_kernel(const float* __restrict__ pair,
                                                       const float* __restrict__ ln_w,
                                                       const float* __restrict__ ln_b,
                                                       const float* __restrict__ Wb) {
    __shared__ float s[16][132];
    int t = threadIdx.x;
    int lane = t & 31;
    int w = t >> 5;
    int n = blockIdx.x * 16 + w;

    const float4 xv = *(const float4*)&pair[(size_t)n * D + lane * 4];
    float sm  = xv.x + xv.y + xv.z + xv.w;
    float sm2 = xv.x * xv.x + xv.y * xv.y + xv.z * xv.z + xv.w * xv.w;
#pragma unroll
    for (int off = 16; off > 0; off >>= 1) {
        sm  += __shfl_xor_sync(0xffffffffu, sm,  off);
        sm2 += __shfl_xor_sync(0xffffffffu, sm2, off);
    }
    float mean = sm * (1.0f / 128.0f);
    float var  = sm2 * (1.0f / 128.0f) - mean * mean;
    float rstd = rsqrtf(var + 1e-5f);
    float4 w4 = *(const float4*)&ln_w[lane * 4];
    float4 b4 = *(const float4*)&ln_b[lane * 4];
    float o0 = (xv.x - mean) * rstd * w4.x + b4.x;
    float o1 = (xv.y - mean) * rstd * w4.y + b4.y;
    float o2 = (xv.z - mean) * rstd * w4.z + b4.z;
    float o3 = (xv.w - mean) * rstd * w4.w + b4.w;

    {
        float xs[4] = {o0, o1, o2, o3};
        float p0 = 0.f, p1 = 0.f, p2 = 0.f, p3 = 0.f;
#pragma unroll
        for (int q = 0; q < 4; q++) {
            float4 wb = *(const float4*)&Wb[(lane * 4 + q) * H];
            p0 += xs[q] * wb.x;
            p1 += xs[q] * wb.y;
            p2 += xs[q] * wb.z;
            p3 += xs[q] * wb.w;
        }
#pragma unroll
        for (int off = 16; off > 0; off >>= 1) {
            p0 += __shfl_xor_sync(0xffffffffu, p0, off);
            p1 += __shfl_xor_sync(0xffffffffu, p1, off);
            p2 += __shfl_xor_sync(0xffffffffu, p2, off);
            p3 += __shfl_xor_sync(0xffffffffu, p3, off);
        }
        if (lane == 0) {
            g_bias[0 * NROW + n] = p0 * LOG2E;
            g_bias[1 * NROW + n] = p1 * LOG2E;
            g_bias[2 * NROW + n] = p2 * LOG2E;
            g_bias[3 * NROW + n] = p3 * LOG2E;
        }
    }

    s[w][lane * 4 + 0] = o0;
    s[w][lane * 4 + 1] = o1;
    s[w][lane * 4 + 2] = o2;
    s[w][lane * 4 + 3] = o3;
    __syncthreads();

    int g  = lane >> 2;
    int tt = lane & 3;
    int ks = w;
    float4 o;
    o.x = to_tf32(s[g][ks * 8 + tt]);
    o.y = to_tf32(s[g + 8][ks * 8 + tt]);
    o.z = to_tf32(s[g][ks * 8 + tt + 4]);
    o.w = to_tf32(s[g + 8][ks * 8 + tt + 4]);
    *(float4*)&g_xp[(size_t)blockIdx.x * 2048 + ks * 128 + lane * 4] = o;
}

// ---------------- W permute -------------------------------------------------
__global__ __launch_bounds__(256) void permute_w_kernel(const float* __restrict__ Wq,
                                                        const float* __restrict__ Wk,
                                                        const float* __restrict__ Wv,
                                                        const float* __restrict__ Wg,
                                                        const float* __restrict__ Wo) {
    const float* srcs[5] = {Wq, Wk, Wv, Wg, Wo};
    const float* W = srcs[blockIdx.x];
    float* dst = g_wp + blockIdx.x * 16384;
    for (int i = threadIdx.x; i < 16384; i += 256) {
        int kk = i >> 7;
        int n  = i & 127;
        int ks = kk >> 3;
        int nt = n >> 3;
        int lane = (n & 7) * 4 + (kk & 3);
        int reg  = (kk >> 2) & 1;
        dst[ks * 1024 + nt * 64 + lane * 2 + reg] = to_tf32(W[i]);
    }
}

// ---------------- 4 projection GEMMs in one grid-parallel launch ------------
__global__ __launch_bounds__(256) void proj_gemm_kernel(const float* __restrict__ Xp,
                                                        const float* __restrict__ bg) {
    __shared__ float As[8][512];
    __shared__ float Bs[4096];

    int t = threadIdx.x;
    int lane = t & 31;
    int warp = t >> 5;
    int warp_m = warp >> 1;
    int warp_n = warp & 1;
    int wsel = blockIdx.y;
    size_t mtb = (size_t)blockIdx.x * 8;
    const float* wp = g_wp + (size_t)wsel * 16384;

    float acc[2][8][4];
#pragma unroll
    for (int wm = 0; wm < 2; wm++)
#pragma unroll
        for (int nt = 0; nt < 8; nt++)
#pragma unroll
            for (int r = 0; r < 4; r++) acc[wm][nt][r] = 0.0f;

    for (int k0s = 0; k0s < 4; k0s++) {
#pragma unroll
        for (int it = 0; it < 4; it++) {
            int f4 = t + it * 256;
            int mt  = f4 >> 7;
            int off = f4 & 127;
            float4 v = *(const float4*)&Xp[((mtb + mt) * 16 + k0s * 4) * 128 + off * 4];
            *(float4*)&As[mt][off * 4] = v;
        }
#pragma unroll
        for (int it = 0; it < 4; it++) {
            int f4 = t + it * 256;
            float4 v = *(const float4*)&wp[k0s * 4096 + f4 * 4];
            *(float4*)&Bs[f4 * 4] = v;
        }
        __syncthreads();

#pragma unroll
        for (int ks = 0; ks < 4; ks++) {
            uint4 afr[2];
            afr[0] = *(const uint4*)&As[warp_m * 2 + 0][ks * 128 + lane * 4];
            afr[1] = *(const uint4*)&As[warp_m * 2 + 1][ks * 128 + lane * 4];
            uint2 bfr[8];
#pragma unroll
            for (int nt = 0; nt < 8; nt++)
                bfr[nt] = *(const uint2*)&Bs[ks * 1024 + (warp_n * 8 + nt) * 64 + lane * 2];
#pragma unroll
            for (int wm = 0; wm < 2; wm++)
#pragma unroll
                for (int nt = 0; nt < 8; nt++) {
                    asm volatile(
                        "mma.sync.aligned.m16n8k8.row.col.f32.tf32.tf32.f32 "
                        "{%0,%1,%2,%3}, {%4,%5,%6,%7}, {%8,%9}, {%0,%1,%2,%3};"
                        : "+f"(acc[wm][nt][0]), "+f"(acc[wm][nt][1]),
                          "+f"(acc[wm][nt][2]), "+f"(acc[wm][nt][3])
                        : "r"(afr[wm].x), "r"(afr[wm].y), "r"(afr[wm].z), "r"(afr[wm].w),
                          "r"(bfr[nt].x), "r"(bfr[nt].y));
                }
        }
        __syncthreads();
    }

    const float qscale = 0.17677669529663687f * LOG2E;
    float* out = (wsel == 0) ? g_q : (wsel == 1) ? g_k : (wsel == 2) ? g_v : g_gate;
    int g   = lane >> 2;
    int tid = lane & 3;
    int m0 = blockIdx.x * 128;
#pragma unroll
    for (int wm = 0; wm < 2; wm++) {
        int row0 = m0 + warp_m * 32 + wm * 16 + g;
#pragma unroll
        for (int nt = 0; nt < 8; nt++) {
            int col = warp_n * 64 + nt * 8 + tid * 2;
            float b0 = 0.f, b1 = 0.f;
            if (wsel == 3) { b0 = bg[col]; b1 = bg[col + 1]; }
            float v[4];
#pragma unroll
            for (int r = 0; r < 4; r++) {
                float a = acc[wm][nt][r];
                if (wsel == 0)      a *= qscale;
                else if (wsel == 3) a = 1.0f / (1.0f + __expf(-(a + ((r & 1) ? b1 : b0))));
                v[r] = a;
            }
            *(float2*)&out[(size_t)row0 * 128 + col]       = make_float2(v[0], v[1]);
            *(float2*)&out[(size_t)(row0 + 8) * 128 + col] = make_float2(v[2], v[3]);
        }
    }
}

// ---------------- attention operand permute (fp16 fragments) ----------------
// Per (i,h), each of q/k/v becomes 4096 packed-half2 words:
//  Q (A-frag m16n8k16): [mt16][ks2][lane*4+reg] = {Q(row, d), Q(row, d+1)}
//    row = mt*16 + (reg&1)*8 + g, d = ks*16 + ((reg>>1)&1)*8 + 2t
//  K (B-frag): [ntg32][ks2][lane*2+reg] = {K(key, d), K(key, d+1)}
//    key = ntg*8 + g, d = ks*16 + reg*8 + 2t
//  V (B-frag): [kc16][ntd4][lane*2+reg] = {V(key, d), V(key+1, d)}
//    key = kc*16 + reg*8 + 2t, d = ntd*8 + g
__global__ __launch_bounds__(256) void attn_permute_kernel() {
    __shared__ float s[256][33];
    int t = threadIdx.x;
    int i = blockIdx.x;
    int h = blockIdx.y;
    size_t src_off = ((size_t)i * 256) * 128 + h * 32;
    size_t base = ((size_t)(i * 4 + h)) * 4096;

    const float* sq = g_q + src_off;
    const float* sk = g_k + src_off;
    const float* sv = g_v + src_off;

#pragma unroll 1
    for (int phase = 0; phase < 3; phase++) {
        const float* src = (phase == 0) ? sq : (phase == 1) ? sk : sv;
        unsigned int* dst = (phase == 0) ? (g_qp16 + base)
                           : (phase == 1) ? (g_kp16 + base) : (g_vp16 + base);
#pragma unroll
        for (int it = 0; it < 8; it++) {
            int f4 = t + it * 256;
            int r  = f4 >> 3;
            int c4 = f4 & 7;
            float4 v = *(const float4*)&src[(size_t)r * 128 + c4 * 4];
            s[r][c4 * 4 + 0] = v.x;
            s[r][c4 * 4 + 1] = v.y;
            s[r][c4 * 4 + 2] = v.z;
            s[r][c4 * 4 + 3] = v.w;
        }
        __syncthreads();
        if (phase == 0) {
#pragma unroll
            for (int it = 0; it < 16; it++) {
                int idx = it * 256 + t;
                int mt   = idx >> 8;
                int ks   = (idx >> 7) & 1;
                int lane = (idx >> 2) & 31;
                int reg  = idx & 3;
                int g2 = lane >> 2, t2 = lane & 3;
                int row = mt * 16 + (reg & 1) * 8 + g2;
                int d   = ks * 16 + ((reg >> 1) & 1) * 8 + 2 * t2;
                dst[idx] = pack_h2(s[row][d], s[row][d + 1]);
            }
        } else if (phase == 1) {
#pragma unroll
            for (int it = 0; it < 16; it++) {
                int idx = it * 256 + t;
                int ntg  = idx >> 7;
                int ks   = (idx >> 6) & 1;
                int lane = (idx >> 1) & 31;
                int reg  = idx & 1;
                int g2 = lane >> 2, t2 = lane & 3;
                int key = ntg * 8 + g2;
                int d   = ks * 16 + reg * 8 + 2 * t2;
                dst[idx] = pack_h2(s[key][d], s[key][d + 1]);
            }
        } else {
#pragma unroll
            for (int it = 0; it < 16; it++) {
                int idx = it * 256 + t;
                int kc   = idx >> 8;
                int ntd  = (idx >> 6) & 3;
                int lane = (idx >> 1) & 31;
                int reg  = idx & 1;
                int g2 = lane >> 2, t2 = lane & 3;
                int key = kc * 16 + reg * 8 + 2 * t2;
                int d   = ntd * 8 + g2;
                dst[idx] = pack_h2(s[key][d], s[key + 1][d]);
            }
        }
        __syncthreads();
    }
}

// ---------------- fp16 tensor-core attention (K/V staged in shared) ---------
// grid (i=256, jt=2, h=4); 8 warps; warp handles 16 j-rows.
// smem (dynamic, u32 view): Ks16[4096] + Vs16[4096] + Pb16[8*256] = 40 KB.
__global__ __launch_bounds__(256) void attn_mma_kernel() {
    extern __shared__ unsigned int shu[];
    unsigned int* Ks16 = shu;           // 4096
    unsigned int* Vs16 = shu + 4096;    // 4096
    unsigned int* Pall = shu + 8192;    // 8*256

    int t = threadIdx.x;
    int lane = t & 31;
    int warp = t >> 5;
    int g  = lane >> 2;
    int tq = lane & 3;
    int i  = blockIdx.x;
    int jt = blockIdx.y;
    int h  = blockIdx.z;

    size_t base = ((size_t)(i * 4 + h)) * 4096;
    const unsigned int* qp = g_qp16 + base;
    const unsigned int* kp = g_kp16 + base;
    const unsigned int* vp = g_vp16 + base;

    // stage K and V fragment buffers (coalesced; 1024 uint4 each)
#pragma unroll
    for (int it = 0; it < 4; it++) {
        int f4 = t + it * 256;
        *(uint4*)&Ks16[f4 * 4] = *(const uint4*)&kp[f4 * 4];
    }
#pragma unroll
    for (int it = 0; it < 4; it++) {
        int f4 = t + it * 256;
        *(uint4*)&Vs16[f4 * 4] = *(const uint4*)&vp[f4 * 4];
    }

    int mt_global = jt * 8 + warp;
    int j0 = mt_global * 16;

    uint4 qf[2];
#pragma unroll
    for (int ks = 0; ks < 2; ks++)
        qf[ks] = *(const uint4*)&qp[mt_global * 256 + ks * 128 + lane * 4];

    const float* brow0 = g_bias + (size_t)h * NROW + (size_t)(j0 + g) * 256;
    const float* brow1 = brow0 + 8 * 256;

    float lsum0 = 0.f, lsum1 = 0.f;
    float oacc[4][4];
#pragma unroll
    for (int nt = 0; nt < 4; nt++)
#pragma unroll
        for (int r = 0; r < 4; r++) oacc[nt][r] = 0.f;

    unsigned int* pb = &Pall[warp * 256];

    __syncthreads();

    for (int c = 0; c < 8; c++) {
        // ---- QK^T (fp16 m16n8k16) + bias + exp2 -> packed P -------------
#pragma unroll
        for (int nt = 0; nt < 4; nt++) {
            float sacc[4] = {0.f, 0.f, 0.f, 0.f};
#pragma unroll
            for (int ks = 0; ks < 2; ks++) {
                uint2 kf = *(const uint2*)&Ks16[((c * 4 + nt) * 2 + ks) * 64 + lane * 2];
                asm volatile(
                    "mma.sync.aligned.m16n8k16.row.col.f32.f16.f16.f32 "
                    "{%0,%1,%2,%3}, {%4,%5,%6,%7}, {%8,%9}, {%0,%1,%2,%3};"
                    : "+f"(sacc[0]), "+f"(sacc[1]), "+f"(sacc[2]), "+f"(sacc[3])
                    : "r"(qf[ks].x), "r"(qf[ks].y), "r"(qf[ks].z), "r"(qf[ks].w),
                      "r"(kf.x), "r"(kf.y));
            }
            int keyc = c * 32 + nt * 8 + tq * 2;
            float2 b0 = *(const float2*)&brow0[keyc];
            float2 b1 = *(const float2*)&brow1[keyc];
            float p0 = fast_ex2(sacc[0] + b0.x);
            float p1 = fast_ex2(sacc[1] + b0.y);
            float p2 = fast_ex2(sacc[2] + b1.x);
            float p3 = fast_ex2(sacc[3] + b1.y);
            lsum0 += p0 + p1;
            lsum1 += p2 + p3;
            // packed A-frag P: keys (2tq,2tq+1) at rows g and g+8
            pb[nt * 64 + g * 4 + tq]        = pack_h2(p0, p1);
            pb[nt * 64 + (g + 8) * 4 + tq]  = pack_h2(p2, p3);
        }
        __syncwarp();
        // ---- P V (fp16 m16n8k16): two 16-key chunks per c-iter -----------
#pragma unroll
        for (int cc = 0; cc < 2; cc++) {
            unsigned int pa0 = pb[(2 * cc) * 64 + g * 4 + tq];
            unsigned int pa1 = pb[(2 * cc) * 64 + (g + 8) * 4 + tq];
            unsigned int pa2 = pb[(2 * cc + 1) * 64 + g * 4 + tq];
            unsigned int pa3 = pb[(2 * cc + 1) * 64 + (g + 8) * 4 + tq];
#pragma unroll
            for (int ntd = 0; ntd < 4; ntd++) {
                uint2 vf = *(const uint2*)&Vs16[((c * 2 + cc) * 4 + ntd) * 64 + lane * 2];
                asm volatile(
                    "mma.sync.aligned.m16n8k16.row.col.f32.f16.f16.f32 "
                    "{%0,%1,%2,%3}, {%4,%5,%6,%7}, {%8,%9}, {%0,%1,%2,%3};"
                    : "+f"(oacc[ntd][0]), "+f"(oacc[ntd][1]),
                      "+f"(oacc[ntd][2]), "+f"(oacc[ntd][3])
                    : "r"(pa0), "r"(pa1), "r"(pa2), "r"(pa3),
                      "r"(vf.x), "r"(vf.y));
            }
        }
        __syncwarp();
    }

    lsum0 += __shfl_xor_sync(0xffffffffu, lsum0, 1);
    lsum0 += __shfl_xor_sync(0xffffffffu, lsum0, 2);
    lsum1 += __shfl_xor_sync(0xffffffffu, lsum1, 1);
    lsum1 += __shfl_xor_sync(0xffffffffu, lsum1, 2);
    float inv0 = 1.0f / lsum0;
    float inv1 = 1.0f / lsum1;

    // ---- gated output -> tf32 A-frag staging (reuse Ks/Vs region) ----------
    __syncthreads();
    float* pbf = (float*)shu + warp * 512;
    int e0 = (2 * tq) & 3;
    int e1 = (2 * tq + 1) & 3;
    size_t row0 = (size_t)(i * 256 + j0 + g) * 128 + h * 32;
    size_t row1 = row0 + 8 * 128;
#pragma unroll
    for (int ntd = 0; ntd < 4; ntd++) {
        int col = ntd * 8 + tq * 2;
        float2 g0 = *(const float2*)&g_gate[row0 + col];
        float2 g1 = *(const float2*)&g_gate[row1 + col];
        float v0 = oacc[ntd][0] * inv0 * g0.x;
        float v1 = oacc[ntd][1] * inv0 * g0.y;
        float v2 = oacc[ntd][2] * inv1 * g1.x;
        float v3 = oacc[ntd][3] * inv1 * g1.y;
        pbf[ntd * 128 + (g * 4 + e0) * 4 + 0 + 2 * (tq >> 1)] = to_tf32(v0);
        pbf[ntd * 128 + (g * 4 + e1) * 4 + 0 + 2 * (tq >> 1)] = to_tf32(v1);
        pbf[ntd * 128 + (g * 4 + e0) * 4 + 1 + 2 * (tq >> 1)] = to_tf32(v2);
        pbf[ntd * 128 + (g * 4 + e1) * 4 + 1 + 2 * (tq >> 1)] = to_tf32(v3);
    }
    __syncwarp();
    size_t tile = (size_t)(i * 16 + mt_global);
    float* dst = g_goutp + tile * 2048 + h * 512;
#pragma unroll
    for (int q = 0; q < 4; q++) {
        *(float4*)&dst[(q * 32 + lane) * 4] = *(const float4*)&pbf[(q * 32 + lane) * 4];
    }
}

// ---------------- final output GEMM -----------------------------------------
__global__ __launch_bounds__(256) void gemm_tf32_kernel(const float* __restrict__ Xp,
                                                        int wsel,
                                                        float* __restrict__ out,
                                                        const float* __restrict__ bias) {
    __shared__ float As[8][512];
    __shared__ float Bs[4096];

    int t = threadIdx.x;
    int lane = t & 31;
    int warp = t >> 5;
    int warp_m = warp >> 1;
    int warp_n = warp & 1;
    size_t mtb = (size_t)blockIdx.x * 8;
    const float* wp = g_wp + (size_t)wsel * 16384;

    float acc[2][8][4];
#pragma unroll
    for (int wm = 0; wm < 2; wm++)
#pragma unroll
        for (int nt = 0; nt < 8; nt++)
#pragma unroll
            for (int r = 0; r < 4; r++) acc[wm][nt][r] = 0.0f;

    for (int k0s = 0; k0s < 4; k0s++) {
#pragma unroll
        for (int it = 0; it < 4; it++) {
            int f4 = t + it * 256;
            int mt  = f4 >> 7;
            int off = f4 & 127;
            float4 v = *(const float4*)&Xp[((mtb + mt) * 16 + k0s * 4) * 128 + off * 4];
            *(float4*)&As[mt][off * 4] = v;
        }
#pragma unroll
        for (int it = 0; it < 4; it++) {
            int f4 = t + it * 256;
            float4 v = *(const float4*)&wp[k0s * 4096 + f4 * 4];
            *(float4*)&Bs[f4 * 4] = v;
        }
        __syncthreads();

#pragma unroll
        for (int ks = 0; ks < 4; ks++) {
            uint4 afr[2];
            afr[0] = *(const uint4*)&As[warp_m * 2 + 0][ks * 128 + lane * 4];
            afr[1] = *(const uint4*)&As[warp_m * 2 + 1][ks * 128 + lane * 4];
            uint2 bfr[8];
#pragma unroll
            for (int nt = 0; nt < 8; nt++)
                bfr[nt] = *(const uint2*)&Bs[ks * 1024 + (warp_n * 8 + nt) * 64 + lane * 2];
#pragma unroll
            for (int wm = 0; wm < 2; wm++)
#pragma unroll
                for (int nt = 0; nt < 8; nt++) {
                    asm volatile(
                        "mma.sync.aligned.m16n8k8.row.col.f32.tf32.tf32.f32 "
                        "{%0,%1,%2,%3}, {%4,%5,%6,%7}, {%8,%9}, {%0,%1,%2,%3};"
                        : "+f"(acc[wm][nt][0]), "+f"(acc[wm][nt][1]),
                          "+f"(acc[wm][nt][2]), "+f"(acc[wm][nt][3])
                        : "r"(afr[wm].x), "r"(afr[wm].y), "r"(afr[wm].z), "r"(afr[wm].w),
                          "r"(bfr[nt].x), "r"(bfr[nt].y));
                }
        }
        __syncthreads();
    }

    int g   = lane >> 2;
    int tid = lane & 3;
    int m0 = blockIdx.x * 128;
#pragma unroll
    for (int wm = 0; wm < 2; wm++) {
        int row0 = m0 + warp_m * 32 + wm * 16 + g;
#pragma unroll
        for (int nt = 0; nt < 8; nt++) {
            int col = warp_n * 64 + nt * 8 + tid * 2;
            float b0 = bias[col], b1 = bias[col + 1];
            *(float2*)&out[(size_t)row0 * 128 + col] =
                make_float2(acc[wm][nt][0] + b0, acc[wm][nt][1] + b1);
            *(float2*)&out[(size_t)(row0 + 8) * 128 + col] =
                make_float2(acc[wm][nt][2] + b0, acc[wm][nt][3] + b1);
        }
    }
}

// ---------------- launch ----------------------------------------------------
extern "C" void kernel_launch(void* const* d_in, const int* in_sizes, int n_in,
                              void* d_out, int out_size) {
    const float* pair = (const float*)d_in[0];
    const float* ln_w = (const float*)d_in[1];
    const float* ln_b = (const float*)d_in[2];
    const float* Wq   = (const float*)d_in[3];
    const float* Wk   = (const float*)d_in[4];
    const float* Wv   = (const float*)d_in[5];
    const float* Wb   = (const float*)d_in[6];
    const float* Wg   = (const float*)d_in[7];
    const float* bg   = (const float*)d_in[8];
    const float* Wo   = (const float*)d_in[9];
    const float* bo   = (const float*)d_in[10];
    float* out = (float*)d_out;

    float *pxp, *pgoutp;
    cudaGetSymbolAddress((void**)&pxp,    g_xp);
    cudaGetSymbolAddress((void**)&pgoutp, g_goutp);

    cudaFuncSetAttribute(attn_mma_kernel, cudaFuncAttributeMaxDynamicSharedMemorySize,
                         (4096 + 4096 + 8 * 256) * (int)sizeof(unsigned int));

    ln_fused_kernel<<<NROW / 16, 512>>>(pair, ln_w, ln_b, Wb);
    permute_w_kernel<<<5, 256>>>(Wq, Wk, Wv, Wg, Wo);

    proj_gemm_kernel<<<dim3(NROW / 128, 4), 256>>>(pxp, bg);

    attn_permute_kernel<<<dim3(L, H), 256>>>();
    attn_mma_kernel<<<dim3(L, 2, H), 256,
                      (4096 + 4096 + 8 * 256) * sizeof(unsigned int)>>>();

    gemm_tf32_kernel<<<NROW / 128, 256>>>(pgoutp, 4, out, bo);
}